// round 14
// baseline (speedup 1.0000x reference)
#include <cuda_runtime.h>
#include <cuda_fp16.h>
#include <math.h>
#include <stdint.h>

#define BB 8
#define TT 2048
#define CC 512
#define NNODE 1024

// ============================ scratch (static) ============================
#define AL __align__(128)
__device__ AL __half g_xh[BB * TT * CC];
__device__ AL __half g_xl[BB * TT * CC];
__device__ AL __half g_xTh[BB * CC * TT];
__device__ AL __half g_xTl[BB * CC * TT];
__device__ AL __half g_Wqh[NNODE * TT];
__device__ AL __half g_Wql[NNODE * TT];
__device__ AL __half g_WkTh[CC * CC];    // Wk transposed [c, d], hi/lo
__device__ AL __half g_WkTl[CC * CC];
__device__ AL __half g_MTh[CC * CC];     // MT = Wout @ Wv  (row d', col c), hi/lo
__device__ AL __half g_MTl[CC * CC];
__device__ AL __half g_sh[BB * NNODE * CC];  // qWk[n,c] hilo
__device__ AL __half g_sl[BB * NNODE * CC];
__device__ AL __half g_qh[BB * NNODE * CC];
__device__ AL __half g_ql[BB * NNODE * CC];
__device__ AL float g_vw[BB * TT * CC];  // vw = x @ MT^T  (= v @ Wout^T)
__device__ AL unsigned long long g_colmax[BB * TT];
__device__ AL unsigned int g_Mkey[BB * NNODE];
__device__ AL float g_Z[BB * NNODE];

// ============================ helpers ============================
__device__ __forceinline__ unsigned int fkey(float f) {
    unsigned int u = __float_as_uint(f);
    return (u & 0x80000000u) ? ~u : (u | 0x80000000u);
}
__device__ __forceinline__ float funkey(unsigned int u) {
    unsigned int v = (u & 0x80000000u) ? (u & 0x7fffffffu) : ~u;
    return __uint_as_float(v);
}
__device__ __forceinline__ uint32_t smem_u32(const void* p) {
    uint32_t a;
    asm("{ .reg .u64 t; cvta.to.shared.u64 t, %1; cvt.u32.u64 %0, t; }" : "=r"(a) : "l"(p));
    return a;
}
__device__ __forceinline__ void cp16(uint32_t dst, const void* src) {
    asm volatile("cp.async.cg.shared.global [%0], [%1], 16;" :: "r"(dst), "l"(src) : "memory");
}
__device__ __forceinline__ void cp_commit() {
    asm volatile("cp.async.commit_group;" ::: "memory");
}
template <int N> __device__ __forceinline__ void cp_wait() {
    asm volatile("cp.async.wait_group %0;" :: "n"(N) : "memory");
}
__device__ __forceinline__ void mma16(float* d,
                                      unsigned a0, unsigned a1, unsigned a2, unsigned a3,
                                      unsigned b0, unsigned b1) {
    asm volatile(
        "mma.sync.aligned.m16n8k16.row.col.f32.f16.f16.f32 "
        "{%0,%1,%2,%3},{%4,%5,%6,%7},{%8,%9},{%0,%1,%2,%3};"
        : "+f"(d[0]), "+f"(d[1]), "+f"(d[2]), "+f"(d[3])
        : "r"(a0), "r"(a1), "r"(a2), "r"(a3), "r"(b0), "r"(b1));
}
__device__ __forceinline__ void ldmx4(unsigned& r0, unsigned& r1, unsigned& r2, unsigned& r3,
                                      uint32_t addr) {
    asm volatile("ldmatrix.sync.aligned.m8n8.x4.shared.b16 {%0,%1,%2,%3}, [%4];"
                 : "=r"(r0), "=r"(r1), "=r"(r2), "=r"(r3) : "r"(addr));
}
__device__ __forceinline__ void split_h(float v, __half& h, __half& l) {
    h = __float2half_rn(v);
    l = __float2half_rn(v - __half2float(h));
}
__device__ __forceinline__ unsigned packh2(__half a, __half b) {
    __half2 t = __halves2half2(a, b);
    return *reinterpret_cast<unsigned*>(&t);
}

// ============================ fp16 split mma.sync NT GEMM ============================
// NTERM=3: ah*bh + ah*bl + al*bh.  NTERM=2: ah*bh + al*bh (B-lo dropped, tile not loaded).
// Block 128x128, BK=32 halves, 8 warps 2(m) x 4(n), warp tile 64x32.
// EPI: 0 plain->Cp, 2 hilo->Ch/Cl, 3 hilo+rowbias->Ch/Cl, 4 argmax->colmax
static const int SROWB = 80;
static const int TILE_B = 128 * SROWB;              // 10240
static const int STAGE_B = 4 * TILE_B;              // 40960
static const int RED_OFF = 2 * STAGE_B;             // 81920
static const int SMEM_SZ = RED_OFF + 1024;          // 82944

template <int EPI, int NTERM>
__global__ __launch_bounds__(256, 2) void gemm_mma(
    const __half* __restrict__ Ahp, const __half* __restrict__ Alp,
    const __half* __restrict__ Bhp, const __half* __restrict__ Blp,
    const float* __restrict__ bias,
    float* __restrict__ Cp, __half* __restrict__ Ch, __half* __restrict__ Cl,
    int Nd, int K,
    long sAz, long sBz, long sCz,
    float scale, unsigned long long* colmax, long sMz)
{
    extern __shared__ __align__(16) char smem[];
    const uint32_t sb = smem_u32(smem);
    const int tid = threadIdx.x;
    const int lane = tid & 31;
    const int wid = tid >> 5;
    const int wm = wid >> 2;
    const int wn = wid & 3;
    const int grp = lane >> 2;
    const int qd = lane & 3;
    const int z = blockIdx.z;
    const long m0 = (long)blockIdx.y * 128;
    const long n0 = (long)blockIdx.x * 128;

    const __half* pT[4] = { Ahp + z * sAz + m0 * K, Alp + z * sAz + m0 * K,
                            Bhp + z * sBz + n0 * K, Blp + z * sBz + n0 * K };
    const __half* src[8];
    uint32_t dst[8];
#pragma unroll
    for (int i = 0; i < 8; i++) {
        int w = i * 256 + tid;
        int tile = w >> 9;
        int row = (w >> 2) & 127;
        int ch = w & 3;
        src[i] = pT[tile] + (long)row * K + ch * 8;
        dst[i] = tile * TILE_B + row * SROWB + ch * 16;
    }

    const int nKB = K >> 5;

#pragma unroll
    for (int i = 0; i < 8; i++)
        if (NTERM == 3 || i < 6) cp16(sb + dst[i], src[i]);
    cp_commit();

    float acc[4][4][4];
#pragma unroll
    for (int mf = 0; mf < 4; mf++)
#pragma unroll
        for (int nf = 0; nf < 4; nf++)
#pragma unroll
            for (int r = 0; r < 4; r++) acc[mf][nf][r] = 0.f;

    const int lrow = lane & 15;
    const int lcol = (lane >> 4) * 8;

    for (int kb = 0; kb < nKB; kb++) {
        cp_wait<0>();
        __syncthreads();
        if (kb + 1 < nKB) {
            uint32_t so = ((kb + 1) & 1) * STAGE_B;
            const long ko = (long)(kb + 1) * 32;
#pragma unroll
            for (int i = 0; i < 8; i++)
                if (NTERM == 3 || i < 6) cp16(sb + so + dst[i], src[i] + ko);
            cp_commit();
        }

        const uint32_t stg = sb + (kb & 1) * STAGE_B;
        const uint32_t sAh = stg, sAl = stg + TILE_B;
        const uint32_t sBh = stg + 2 * TILE_B, sBl = stg + 3 * TILE_B;

#pragma unroll
        for (int ks = 0; ks < 2; ks++) {
            const int k0 = ks * 16;
            const uint32_t cofs = (lcol + k0) * 2;
            unsigned rbh[2][4], rbl[2][4];
#pragma unroll
            for (int nfp = 0; nfp < 2; nfp++) {
                uint32_t ro = (uint32_t)(wn * 32 + nfp * 16 + lrow) * SROWB + cofs;
                ldmx4(rbh[nfp][0], rbh[nfp][1], rbh[nfp][2], rbh[nfp][3], sBh + ro);
                if (NTERM == 3)
                    ldmx4(rbl[nfp][0], rbl[nfp][1], rbl[nfp][2], rbl[nfp][3], sBl + ro);
            }
#pragma unroll
            for (int mf = 0; mf < 4; mf++) {
                uint32_t ro = (uint32_t)(wm * 64 + mf * 16 + lrow) * SROWB + cofs;
                unsigned ah0, ah1, ah2, ah3, al0, al1, al2, al3;
                ldmx4(ah0, ah1, ah2, ah3, sAh + ro);
                ldmx4(al0, al1, al2, al3, sAl + ro);
#pragma unroll
                for (int nfp = 0; nfp < 2; nfp++)
#pragma unroll
                    for (int sub = 0; sub < 2; sub++)
                        mma16(acc[mf][nfp * 2 + sub], ah0, ah1, ah2, ah3,
                              rbh[nfp][sub], rbh[nfp][sub + 2]);
                if (NTERM == 3) {
#pragma unroll
                    for (int nfp = 0; nfp < 2; nfp++)
#pragma unroll
                        for (int sub = 0; sub < 2; sub++)
                            mma16(acc[mf][nfp * 2 + sub], ah0, ah1, ah2, ah3,
                                  rbl[nfp][sub], rbl[nfp][sub + 2]);
                }
#pragma unroll
                for (int nfp = 0; nfp < 2; nfp++)
#pragma unroll
                    for (int sub = 0; sub < 2; sub++)
                        mma16(acc[mf][nfp * 2 + sub], al0, al1, al2, al3,
                              rbh[nfp][sub], rbh[nfp][sub + 2]);
            }
        }
    }

    // ---------------- epilogue ----------------
    if constexpr (EPI == 4) {
        unsigned long long* red = (unsigned long long*)(smem + RED_OFF);
        __syncthreads();
        if (tid < 128) red[tid] = 0ull;
        __syncthreads();
#pragma unroll
        for (int mf = 0; mf < 4; mf++) {
#pragma unroll
            for (int half = 0; half < 2; half++) {
                int lr = wm * 64 + mf * 16 + grp + half * 8;
                float bv = -INFINITY; int bc = 0;
#pragma unroll
                for (int nf = 0; nf < 4; nf++) {
#pragma unroll
                    for (int c = 0; c < 2; c++) {
                        float vv = acc[mf][nf][half * 2 + c];
                        int col = (int)n0 + wn * 32 + nf * 8 + qd * 2 + c;
                        if (vv > bv) { bv = vv; bc = col; }
                    }
                }
                unsigned long long pack =
                    ((unsigned long long)fkey(bv * scale) << 32) | (unsigned int)bc;
                unsigned long long o;
                o = __shfl_xor_sync(0xffffffffu, pack, 1); if (o > pack) pack = o;
                o = __shfl_xor_sync(0xffffffffu, pack, 2); if (o > pack) pack = o;
                if (qd == 0) atomicMax(&red[lr], pack);
            }
        }
        __syncthreads();
        if (tid < 128)
            atomicMax(&colmax[z * sMz + m0 + tid], red[tid]);
    } else {
#pragma unroll
        for (int mf = 0; mf < 4; mf++) {
#pragma unroll
            for (int half = 0; half < 2; half++) {
                long row = m0 + wm * 64 + mf * 16 + grp + half * 8;
                float rb = 0.f;
                if constexpr (EPI == 3) rb = bias[row];
                long base = z * sCz + row * (long)Nd + n0 + wn * 32 + qd * 2;
#pragma unroll
                for (int nf = 0; nf < 4; nf++) {
                    float v0 = acc[mf][nf][half * 2 + 0];
                    float v1 = acc[mf][nf][half * 2 + 1];
                    long off = base + nf * 8;
                    if constexpr (EPI == 0) {
                        *reinterpret_cast<float2*>(&Cp[off]) = make_float2(v0, v1);
                    } else {
                        v0 += rb; v1 += rb;
                        __half h0, l0, h1, l1;
                        split_h(v0, h0, l0);
                        split_h(v1, h1, l1);
                        *reinterpret_cast<__half2*>(&Ch[off]) = __halves2half2(h0, h1);
                        *reinterpret_cast<__half2*>(&Cl[off]) = __halves2half2(l0, l1);
                    }
                }
            }
        }
    }
}

// ============================ small kernels ============================
// init: colmax/Mkey/Z zero, out[b,n,:] = bout (bias pre-init for direct scatter)
__global__ void init_kernel(float* __restrict__ out, const float* __restrict__ bout) {
    int i = blockIdx.x * blockDim.x + threadIdx.x;
    int stride = gridDim.x * blockDim.x;
    for (int j = i; j < BB * TT; j += stride) g_colmax[j] = 0ull;
    for (int j = i; j < BB * NNODE; j += stride) { g_Mkey[j] = 0u; g_Z[j] = 0.f; }
    const int n4 = BB * NNODE * CC / 4;
    const float4* b4 = reinterpret_cast<const float4*>(bout);
    float4* o4 = reinterpret_cast<float4*>(out);
    for (int j = i; j < n4; j += stride) o4[j] = b4[j & (CC / 4 - 1)];
}

// fused: x -> (xh, xl) row-major AND (xTh, xTl) transposed, single read of x.
// Phase 1 vectorized: one float4 load + two uint2 stores per thread.
__global__ void split_x(const float* __restrict__ x) {
    __shared__ float tile[32][33];
    const int z = blockIdx.z;
    const int t0 = blockIdx.x * 32, c0 = blockIdx.y * 32;
    const int tid = threadIdx.x;       // 0..255
    const int r = tid >> 3;            // 0..31
    const int q = tid & 7;             // 0..7 (column quad)

    long o = ((long)z * TT + t0 + r) * CC + c0 + 4 * q;
    float4 v = *reinterpret_cast<const float4*>(&x[o]);
    tile[r][4 * q + 0] = v.x; tile[r][4 * q + 1] = v.y;
    tile[r][4 * q + 2] = v.z; tile[r][4 * q + 3] = v.w;
    {
        __half h0, l0, h1, l1, h2, l2, h3, l3;
        split_h(v.x, h0, l0); split_h(v.y, h1, l1);
        split_h(v.z, h2, l2); split_h(v.w, h3, l3);
        *reinterpret_cast<uint2*>(&g_xh[o]) = make_uint2(packh2(h0, h1), packh2(h2, h3));
        *reinterpret_cast<uint2*>(&g_xl[o]) = make_uint2(packh2(l0, l1), packh2(l2, l3));
    }
    __syncthreads();
    // phase 2: transposed write (reads tile[4q+j][r])
    __half hh[4], ll[4];
#pragma unroll
    for (int j = 0; j < 4; j++)
        split_h(tile[4 * q + j][r], hh[j], ll[j]);
    long ob = ((long)z * CC + c0 + r) * TT + t0 + 4 * q;
    *reinterpret_cast<uint2*>(&g_xTh[ob]) = make_uint2(packh2(hh[0], hh[1]), packh2(hh[2], hh[3]));
    *reinterpret_cast<uint2*>(&g_xTl[ob]) = make_uint2(packh2(ll[0], ll[1]), packh2(ll[2], ll[3]));
}

// split Wq (row-major)
__global__ void splitWq(const float* __restrict__ Wq) {
    const long nq4 = (long)NNODE * TT / 4;
    long i = (long)blockIdx.x * blockDim.x + threadIdx.x;
    long stride = (long)gridDim.x * blockDim.x;
    for (long j = i; j < nq4; j += stride) {
        float4 v = reinterpret_cast<const float4*>(Wq)[j];
        __half h0, l0, h1, l1, h2, l2, h3, l3;
        split_h(v.x, h0, l0); split_h(v.y, h1, l1);
        split_h(v.z, h2, l2); split_h(v.w, h3, l3);
        reinterpret_cast<uint2*>(g_Wqh)[j] = make_uint2(packh2(h0, h1), packh2(h2, h3));
        reinterpret_cast<uint2*>(g_Wql)[j] = make_uint2(packh2(l0, l1), packh2(l2, l3));
    }
}

// transpose-split Wk: WkT[c][d] = Wk[d][c], hilo planes
__global__ void splitWkT(const float* __restrict__ Wk) {
    __shared__ float tile[32][33];
    const int d0 = blockIdx.x * 32, c0 = blockIdx.y * 32;
    const int tx = threadIdx.x, ty = threadIdx.y;
#pragma unroll
    for (int i = 0; i < 32; i += 8)
        tile[ty + i][tx] = Wk[(long)(d0 + ty + i) * CC + c0 + tx];
    __syncthreads();
    const int tid = ty * 32 + tx;
    const int cr = tid >> 3;           // 0..31 (c-local)
    const int q = tid & 7;             // 0..7  (d-quad)
    __half hh[4], ll[4];
#pragma unroll
    for (int j = 0; j < 4; j++)
        split_h(tile[4 * q + j][cr], hh[j], ll[j]);
    long ob = (long)(c0 + cr) * CC + d0 + 4 * q;
    *reinterpret_cast<uint2*>(&g_WkTh[ob]) = make_uint2(packh2(hh[0], hh[1]), packh2(hh[2], hh[3]));
    *reinterpret_cast<uint2*>(&g_WkTl[ob]) = make_uint2(packh2(ll[0], ll[1]), packh2(ll[2], ll[3]));
}

// MT[d'][c] = sum_c' Wout[d'][c'] * Wv[c'][c]   (fp32, then hilo split)
// v2: 64x64 block tiles, 16 outputs/thread (ILP 16), grid (8,8)
__global__ void compute_MT(const float* __restrict__ Wv, const float* __restrict__ Wout) {
    __shared__ float As[64][33];
    __shared__ float Bs[32][65];
    const int bx = blockIdx.x, by = blockIdx.y;
    const int tid = threadIdx.x;       // 0..255
    const int rg = tid >> 4;           // 0..15
    const int cg = tid & 15;           // 0..15
    float acc[4][4] = {};
    for (int kt = 0; kt < CC / 32; kt++) {
#pragma unroll
        for (int i = 0; i < 8; i++) {
            int e = tid + 256 * i;
            As[e >> 5][e & 31] = Wout[(long)(by * 64 + (e >> 5)) * CC + kt * 32 + (e & 31)];
            Bs[e >> 6][e & 63] = Wv[(long)(kt * 32 + (e >> 6)) * CC + bx * 64 + (e & 63)];
        }
        __syncthreads();
#pragma unroll
        for (int k = 0; k < 32; k++) {
            float a[4], b[4];
#pragma unroll
            for (int i = 0; i < 4; i++) a[i] = As[rg * 4 + i][k];
#pragma unroll
            for (int j = 0; j < 4; j++) b[j] = Bs[k][cg * 4 + j];
#pragma unroll
            for (int i = 0; i < 4; i++)
#pragma unroll
                for (int j = 0; j < 4; j++)
                    acc[i][j] += a[i] * b[j];
        }
        __syncthreads();
    }
#pragma unroll
    for (int i = 0; i < 4; i++)
#pragma unroll
        for (int j = 0; j < 4; j++) {
            long o = (long)(by * 64 + rg * 4 + i) * CC + bx * 64 + cg * 4 + j;
            __half h, l;
            split_h(acc[i][j], h, l);
            g_MTh[o] = h; g_MTl[o] = l;
        }
}

__global__ void node_max_kernel() {
    int i = blockIdx.x * blockDim.x + threadIdx.x;
    if (i >= BB * TT) return;
    int b = i / TT;
    unsigned long long p = g_colmax[i];
    unsigned int n = (unsigned int)(p & 0xffffffffu);
    atomicMax(&g_Mkey[b * NNODE + n], (unsigned int)(p >> 32));
}

__global__ void node_sum_kernel() {
    int i = blockIdx.x * blockDim.x + threadIdx.x;
    if (i >= BB * TT) return;
    int b = i / TT;
    unsigned long long p = g_colmax[i];
    unsigned int n = (unsigned int)(p & 0xffffffffu);
    int bn = b * NNODE + n;
    float m = funkey((unsigned int)(p >> 32));
    atomicAdd(&g_Z[bn], expf(m - funkey(g_Mkey[bn])));
}

// fused: att[bn][t] = w AND out[bn][:] += w * vw[b,t,:]  (out pre-initialized to bout)
__global__ void scatter_kernel(float* __restrict__ att, float* __restrict__ out) {
    int i = blockIdx.x;            // one block per (b, t)
    int b = i / TT;
    int t = i % TT;
    unsigned long long p = g_colmax[i];
    unsigned int n = (unsigned int)(p & 0xffffffffu);
    int bn = b * NNODE + n;
    float m = funkey((unsigned int)(p >> 32));
    float w = expf(m - funkey(g_Mkey[bn])) / g_Z[bn];
    if (threadIdx.x == 0) att[(long)bn * TT + t] = w;
    const float4* vrow = reinterpret_cast<const float4*>(g_vw + (long)i * CC);
    float* orow = out + (long)bn * CC;
    for (int c4 = threadIdx.x; c4 < CC / 4; c4 += blockDim.x) {
        float4 v4 = vrow[c4];
        atomicAdd(&orow[c4 * 4 + 0], w * v4.x);
        atomicAdd(&orow[c4 * 4 + 1], w * v4.y);
        atomicAdd(&orow[c4 * 4 + 2], w * v4.z);
        atomicAdd(&orow[c4 * 4 + 3], w * v4.w);
    }
}

// ============================ launch ============================
extern "C" void kernel_launch(void* const* d_in, const int* in_sizes, int n_in,
                              void* d_out, int out_size)
{
    const float* x    = (const float*)d_in[0];
    const float* Wq   = (const float*)d_in[1];
    const float* bq   = (const float*)d_in[2];
    const float* Wk   = (const float*)d_in[3];
    const float* Wv   = (const float*)d_in[4];
    const float* Wout = (const float*)d_in[5];
    const float* bout = (const float*)d_in[6];

    float* out = (float*)d_out;
    float* att = out + (long)BB * NNODE * CC;

    __half *xh, *xl, *xTh, *xTl, *Wqh, *Wql, *WkTh, *WkTl, *MTh, *MTl;
    __half *sh, *sl, *qh, *ql;
    float *vwp;
    unsigned long long* cm;
    cudaGetSymbolAddress((void**)&xh, g_xh);     cudaGetSymbolAddress((void**)&xl, g_xl);
    cudaGetSymbolAddress((void**)&xTh, g_xTh);   cudaGetSymbolAddress((void**)&xTl, g_xTl);
    cudaGetSymbolAddress((void**)&Wqh, g_Wqh);   cudaGetSymbolAddress((void**)&Wql, g_Wql);
    cudaGetSymbolAddress((void**)&WkTh, g_WkTh); cudaGetSymbolAddress((void**)&WkTl, g_WkTl);
    cudaGetSymbolAddress((void**)&MTh, g_MTh);   cudaGetSymbolAddress((void**)&MTl, g_MTl);
    cudaGetSymbolAddress((void**)&sh, g_sh);     cudaGetSymbolAddress((void**)&sl, g_sl);
    cudaGetSymbolAddress((void**)&qh, g_qh);     cudaGetSymbolAddress((void**)&ql, g_ql);
    cudaGetSymbolAddress((void**)&vwp, g_vw);
    cudaGetSymbolAddress((void**)&cm, g_colmax);

    cudaFuncSetAttribute(gemm_mma<2,3>, cudaFuncAttributeMaxDynamicSharedMemorySize, SMEM_SZ);
    cudaFuncSetAttribute(gemm_mma<0,2>, cudaFuncAttributeMaxDynamicSharedMemorySize, SMEM_SZ);
    cudaFuncSetAttribute(gemm_mma<3,3>, cudaFuncAttributeMaxDynamicSharedMemorySize, SMEM_SZ);
    cudaFuncSetAttribute(gemm_mma<4,3>, cudaFuncAttributeMaxDynamicSharedMemorySize, SMEM_SZ);

    const float scale = 1.0f / sqrtf((float)CC);

    init_kernel<<<2048, 256>>>(out, bout);
    split_x<<<dim3(TT / 32, CC / 32, BB), 256>>>(x);
    splitWq<<<2048, 256>>>(Wq);
    splitWkT<<<dim3(CC / 32, CC / 32), dim3(32, 8)>>>(Wk);
    compute_MT<<<dim3(CC / 64, CC / 64), 256>>>(Wv, Wout);

    // q[b] = Wq @ xT[b]^T + bq -> hilo (3-term)
    gemm_mma<3,3><<<dim3(4, 8, BB), 256, SMEM_SZ>>>(
        Wqh, Wql, xTh, xTl, bq, nullptr, qh, ql, CC, TT,
        0, (long)CC * TT, (long)NNODE * CC, 0.f, nullptr, 0);
    // qWk[b][n,c] = q[b] @ WkT^T -> hilo (3-term)   (M=1024, N=512, K=512)
    gemm_mma<2,3><<<dim3(4, 8, BB), 256, SMEM_SZ>>>(
        qh, ql, WkTh, WkTl, nullptr, nullptr, sh, sl, CC, CC,
        (long)NNODE * CC, 0, (long)NNODE * CC, 0.f, nullptr, 0);
    // vw = x @ MT^T -> plain fp32 (2-term)
    gemm_mma<0,2><<<dim3(4, 128, 1), 256, SMEM_SZ>>>(
        xh, xl, MTh, MTl, nullptr, vwp, nullptr, nullptr, CC, CC, 0, 0, 0, 0.f, nullptr, 0);
    // sim[b] = scale * x[b] @ qWk[b]^T, token-major, fused argmax (3-term)
    gemm_mma<4,3><<<dim3(NNODE / 128, TT / 128, BB), 256, SMEM_SZ>>>(
        xh, xl, sh, sl, nullptr, nullptr, nullptr, nullptr, NNODE, CC,
        (long)TT * CC, (long)NNODE * CC, 0, scale, cm, (long)TT);

    cudaMemsetAsync(att, 0, (size_t)BB * NNODE * TT * sizeof(float), 0);
    node_max_kernel<<<(BB * TT) / 256, 256>>>();
    node_sum_kernel<<<(BB * TT) / 256, 256>>>();
    scatter_kernel<<<BB * TT, 128>>>(att, out);
}

// round 15
// speedup vs baseline: 1.0738x; 1.0738x over previous
#include <cuda_runtime.h>
#include <cuda_fp16.h>
#include <math.h>
#include <stdint.h>

#define BB 8
#define TT 2048
#define CC 512
#define NNODE 1024

// ============================ scratch (static) ============================
#define AL __align__(128)
__device__ AL __half g_xh[BB * TT * CC];
__device__ AL __half g_xl[BB * TT * CC];
__device__ AL __half g_xTh[BB * CC * TT];
__device__ AL __half g_xTl[BB * CC * TT];
__device__ AL __half g_Wqh[NNODE * TT];
__device__ AL __half g_Wql[NNODE * TT];
__device__ AL __half g_WkTh[CC * CC];    // Wk transposed [c, d], hi/lo
__device__ AL __half g_WkTl[CC * CC];
__device__ AL __half g_MTh[CC * CC];     // MT = Wout @ Wv  (row d', col c), hi/lo
__device__ AL __half g_MTl[CC * CC];
__device__ AL __half g_sh[BB * NNODE * CC];  // qWk[n,c] hilo
__device__ AL __half g_sl[BB * NNODE * CC];
__device__ AL __half g_qh[BB * NNODE * CC];
__device__ AL __half g_ql[BB * NNODE * CC];
__device__ AL float g_vw[BB * TT * CC];  // vw = x @ MT^T  (= v @ Wout^T)
__device__ AL unsigned long long g_colmax[BB * TT];
__device__ AL unsigned int g_Mkey[BB * NNODE];
__device__ AL float g_Z[BB * NNODE];

// ============================ helpers ============================
__device__ __forceinline__ unsigned int fkey(float f) {
    unsigned int u = __float_as_uint(f);
    return (u & 0x80000000u) ? ~u : (u | 0x80000000u);
}
__device__ __forceinline__ float funkey(unsigned int u) {
    unsigned int v = (u & 0x80000000u) ? (u & 0x7fffffffu) : ~u;
    return __uint_as_float(v);
}
__device__ __forceinline__ uint32_t smem_u32(const void* p) {
    uint32_t a;
    asm("{ .reg .u64 t; cvta.to.shared.u64 t, %1; cvt.u32.u64 %0, t; }" : "=r"(a) : "l"(p));
    return a;
}
__device__ __forceinline__ void cp16(uint32_t dst, const void* src) {
    asm volatile("cp.async.cg.shared.global [%0], [%1], 16;" :: "r"(dst), "l"(src) : "memory");
}
__device__ __forceinline__ void cp_commit() {
    asm volatile("cp.async.commit_group;" ::: "memory");
}
template <int N> __device__ __forceinline__ void cp_wait() {
    asm volatile("cp.async.wait_group %0;" :: "n"(N) : "memory");
}
__device__ __forceinline__ void mma16(float* d,
                                      unsigned a0, unsigned a1, unsigned a2, unsigned a3,
                                      unsigned b0, unsigned b1) {
    asm volatile(
        "mma.sync.aligned.m16n8k16.row.col.f32.f16.f16.f32 "
        "{%0,%1,%2,%3},{%4,%5,%6,%7},{%8,%9},{%0,%1,%2,%3};"
        : "+f"(d[0]), "+f"(d[1]), "+f"(d[2]), "+f"(d[3])
        : "r"(a0), "r"(a1), "r"(a2), "r"(a3), "r"(b0), "r"(b1));
}
__device__ __forceinline__ void ldmx4(unsigned& r0, unsigned& r1, unsigned& r2, unsigned& r3,
                                      uint32_t addr) {
    asm volatile("ldmatrix.sync.aligned.m8n8.x4.shared.b16 {%0,%1,%2,%3}, [%4];"
                 : "=r"(r0), "=r"(r1), "=r"(r2), "=r"(r3) : "r"(addr));
}
__device__ __forceinline__ void split_h(float v, __half& h, __half& l) {
    h = __float2half_rn(v);
    l = __float2half_rn(v - __half2float(h));
}
__device__ __forceinline__ unsigned packh2(__half a, __half b) {
    __half2 t = __halves2half2(a, b);
    return *reinterpret_cast<unsigned*>(&t);
}

// ============================ fp16 split mma.sync NT GEMM ============================
// NTERM=3: ah*bh + ah*bl + al*bh.  NTERM=2: ah*bh + al*bh.  NTERM=1: ah*bh only.
// Unused split tiles are not even loaded from gmem.
// Block 128x128, BK=32 halves, 8 warps 2(m) x 4(n), warp tile 64x32.
// EPI: 0 plain->Cp, 2 hilo->Ch/Cl, 3 hilo+rowbias->Ch/Cl, 4 argmax->colmax
static const int SROWB = 80;
static const int TILE_B = 128 * SROWB;              // 10240
static const int STAGE_B = 4 * TILE_B;              // 40960
static const int RED_OFF = 2 * STAGE_B;             // 81920
static const int SMEM_SZ = RED_OFF + 1024;          // 82944

template <int NTERM>
__device__ __forceinline__ bool want_chunk(int i) {
    // chunk pairs: [0,1]=Ah, [2,3]=Al, [4,5]=Bh, [6,7]=Bl
    if (NTERM == 3) return true;
    if (NTERM == 2) return i < 6;
    return (i < 2) || (i >= 4 && i < 6);
}

template <int EPI, int NTERM>
__global__ __launch_bounds__(256, 2) void gemm_mma(
    const __half* __restrict__ Ahp, const __half* __restrict__ Alp,
    const __half* __restrict__ Bhp, const __half* __restrict__ Blp,
    const float* __restrict__ bias,
    float* __restrict__ Cp, __half* __restrict__ Ch, __half* __restrict__ Cl,
    int Nd, int K,
    long sAz, long sBz, long sCz,
    float scale, unsigned long long* colmax, long sMz)
{
    extern __shared__ __align__(16) char smem[];
    const uint32_t sb = smem_u32(smem);
    const int tid = threadIdx.x;
    const int lane = tid & 31;
    const int wid = tid >> 5;
    const int wm = wid >> 2;
    const int wn = wid & 3;
    const int grp = lane >> 2;
    const int qd = lane & 3;
    const int z = blockIdx.z;
    const long m0 = (long)blockIdx.y * 128;
    const long n0 = (long)blockIdx.x * 128;

    const __half* pT[4] = { Ahp + z * sAz + m0 * K, Alp + z * sAz + m0 * K,
                            Bhp + z * sBz + n0 * K, Blp + z * sBz + n0 * K };
    const __half* src[8];
    uint32_t dst[8];
#pragma unroll
    for (int i = 0; i < 8; i++) {
        int w = i * 256 + tid;
        int tile = w >> 9;
        int row = (w >> 2) & 127;
        int ch = w & 3;
        src[i] = pT[tile] + (long)row * K + ch * 8;
        dst[i] = tile * TILE_B + row * SROWB + ch * 16;
    }

    const int nKB = K >> 5;

#pragma unroll
    for (int i = 0; i < 8; i++)
        if (want_chunk<NTERM>(i)) cp16(sb + dst[i], src[i]);
    cp_commit();

    float acc[4][4][4];
#pragma unroll
    for (int mf = 0; mf < 4; mf++)
#pragma unroll
        for (int nf = 0; nf < 4; nf++)
#pragma unroll
            for (int r = 0; r < 4; r++) acc[mf][nf][r] = 0.f;

    const int lrow = lane & 15;
    const int lcol = (lane >> 4) * 8;

    for (int kb = 0; kb < nKB; kb++) {
        cp_wait<0>();
        __syncthreads();
        if (kb + 1 < nKB) {
            uint32_t so = ((kb + 1) & 1) * STAGE_B;
            const long ko = (long)(kb + 1) * 32;
#pragma unroll
            for (int i = 0; i < 8; i++)
                if (want_chunk<NTERM>(i)) cp16(sb + so + dst[i], src[i] + ko);
            cp_commit();
        }

        const uint32_t stg = sb + (kb & 1) * STAGE_B;
        const uint32_t sAh = stg, sAl = stg + TILE_B;
        const uint32_t sBh = stg + 2 * TILE_B, sBl = stg + 3 * TILE_B;

#pragma unroll
        for (int ks = 0; ks < 2; ks++) {
            const int k0 = ks * 16;
            const uint32_t cofs = (lcol + k0) * 2;
            unsigned rbh[2][4], rbl[2][4];
#pragma unroll
            for (int nfp = 0; nfp < 2; nfp++) {
                uint32_t ro = (uint32_t)(wn * 32 + nfp * 16 + lrow) * SROWB + cofs;
                ldmx4(rbh[nfp][0], rbh[nfp][1], rbh[nfp][2], rbh[nfp][3], sBh + ro);
                if (NTERM == 3)
                    ldmx4(rbl[nfp][0], rbl[nfp][1], rbl[nfp][2], rbl[nfp][3], sBl + ro);
            }
#pragma unroll
            for (int mf = 0; mf < 4; mf++) {
                uint32_t ro = (uint32_t)(wm * 64 + mf * 16 + lrow) * SROWB + cofs;
                unsigned ah0, ah1, ah2, ah3, al0, al1, al2, al3;
                ldmx4(ah0, ah1, ah2, ah3, sAh + ro);
                if (NTERM >= 2)
                    ldmx4(al0, al1, al2, al3, sAl + ro);
                // pass hh (always)
#pragma unroll
                for (int nfp = 0; nfp < 2; nfp++)
#pragma unroll
                    for (int sub = 0; sub < 2; sub++)
                        mma16(acc[mf][nfp * 2 + sub], ah0, ah1, ah2, ah3,
                              rbh[nfp][sub], rbh[nfp][sub + 2]);
                // pass hl
                if (NTERM == 3) {
#pragma unroll
                    for (int nfp = 0; nfp < 2; nfp++)
#pragma unroll
                        for (int sub = 0; sub < 2; sub++)
                            mma16(acc[mf][nfp * 2 + sub], ah0, ah1, ah2, ah3,
                                  rbl[nfp][sub], rbl[nfp][sub + 2]);
                }
                // pass lh
                if (NTERM >= 2) {
#pragma unroll
                    for (int nfp = 0; nfp < 2; nfp++)
#pragma unroll
                        for (int sub = 0; sub < 2; sub++)
                            mma16(acc[mf][nfp * 2 + sub], al0, al1, al2, al3,
                                  rbh[nfp][sub], rbh[nfp][sub + 2]);
                }
            }
        }
    }

    // ---------------- epilogue ----------------
    if constexpr (EPI == 4) {
        unsigned long long* red = (unsigned long long*)(smem + RED_OFF);
        __syncthreads();
        if (tid < 128) red[tid] = 0ull;
        __syncthreads();
#pragma unroll
        for (int mf = 0; mf < 4; mf++) {
#pragma unroll
            for (int half = 0; half < 2; half++) {
                int lr = wm * 64 + mf * 16 + grp + half * 8;
                float bv = -INFINITY; int bc = 0;
#pragma unroll
                for (int nf = 0; nf < 4; nf++) {
#pragma unroll
                    for (int c = 0; c < 2; c++) {
                        float vv = acc[mf][nf][half * 2 + c];
                        int col = (int)n0 + wn * 32 + nf * 8 + qd * 2 + c;
                        if (vv > bv) { bv = vv; bc = col; }
                    }
                }
                unsigned long long pack =
                    ((unsigned long long)fkey(bv * scale) << 32) | (unsigned int)bc;
                unsigned long long o;
                o = __shfl_xor_sync(0xffffffffu, pack, 1); if (o > pack) pack = o;
                o = __shfl_xor_sync(0xffffffffu, pack, 2); if (o > pack) pack = o;
                if (qd == 0) atomicMax(&red[lr], pack);
            }
        }
        __syncthreads();
        if (tid < 128)
            atomicMax(&colmax[z * sMz + m0 + tid], red[tid]);
    } else {
#pragma unroll
        for (int mf = 0; mf < 4; mf++) {
#pragma unroll
            for (int half = 0; half < 2; half++) {
                long row = m0 + wm * 64 + mf * 16 + grp + half * 8;
                float rb = 0.f;
                if constexpr (EPI == 3) rb = bias[row];
                long base = z * sCz + row * (long)Nd + n0 + wn * 32 + qd * 2;
#pragma unroll
                for (int nf = 0; nf < 4; nf++) {
                    float v0 = acc[mf][nf][half * 2 + 0];
                    float v1 = acc[mf][nf][half * 2 + 1];
                    long off = base + nf * 8;
                    if constexpr (EPI == 0) {
                        *reinterpret_cast<float2*>(&Cp[off]) = make_float2(v0, v1);
                    } else {
                        v0 += rb; v1 += rb;
                        __half h0, l0, h1, l1;
                        split_h(v0, h0, l0);
                        split_h(v1, h1, l1);
                        *reinterpret_cast<__half2*>(&Ch[off]) = __halves2half2(h0, h1);
                        *reinterpret_cast<__half2*>(&Cl[off]) = __halves2half2(l0, l1);
                    }
                }
            }
        }
    }
}

// ============================ small kernels (R13 versions) ============================
// init: colmax/Mkey/Z zero, out[b,n,:] = bout (bias pre-init for direct scatter)
__global__ void init_kernel(float* __restrict__ out, const float* __restrict__ bout) {
    int i = blockIdx.x * blockDim.x + threadIdx.x;
    int stride = gridDim.x * blockDim.x;
    for (int j = i; j < BB * TT; j += stride) g_colmax[j] = 0ull;
    for (int j = i; j < BB * NNODE; j += stride) { g_Mkey[j] = 0u; g_Z[j] = 0.f; }
    const int n4 = BB * NNODE * CC / 4;
    const float4* b4 = reinterpret_cast<const float4*>(bout);
    float4* o4 = reinterpret_cast<float4*>(out);
    for (int j = i; j < n4; j += stride) o4[j] = b4[j & (CC / 4 - 1)];
}

// fused: x -> (xh, xl) row-major AND (xTh, xTl) transposed, single read of x
__global__ void split_x(const float* __restrict__ x) {
    __shared__ float tile[32][33];
    const int z = blockIdx.z;
    const int t0 = blockIdx.x * 32, c0 = blockIdx.y * 32;
    const int tx = threadIdx.x, ty = threadIdx.y;
#pragma unroll
    for (int i = 0; i < 32; i += 8) {
        long o = ((long)z * TT + t0 + ty + i) * CC + c0 + tx;
        float v = x[o];
        tile[ty + i][tx] = v;
        __half h, l;
        split_h(v, h, l);
        g_xh[o] = h; g_xl[o] = l;
    }
    __syncthreads();
    const int tid = ty * 32 + tx;
    const int cr = tid >> 3;
    const int q = tid & 7;
    __half hh[4], ll[4];
#pragma unroll
    for (int j = 0; j < 4; j++)
        split_h(tile[4 * q + j][cr], hh[j], ll[j]);
    long ob = ((long)z * CC + c0 + cr) * TT + t0 + 4 * q;
    *reinterpret_cast<uint2*>(&g_xTh[ob]) = make_uint2(packh2(hh[0], hh[1]), packh2(hh[2], hh[3]));
    *reinterpret_cast<uint2*>(&g_xTl[ob]) = make_uint2(packh2(ll[0], ll[1]), packh2(ll[2], ll[3]));
}

// split Wq (row-major)
__global__ void splitWq(const float* __restrict__ Wq) {
    const long nq4 = (long)NNODE * TT / 4;
    long i = (long)blockIdx.x * blockDim.x + threadIdx.x;
    long stride = (long)gridDim.x * blockDim.x;
    for (long j = i; j < nq4; j += stride) {
        float4 v = reinterpret_cast<const float4*>(Wq)[j];
        __half h0, l0, h1, l1, h2, l2, h3, l3;
        split_h(v.x, h0, l0); split_h(v.y, h1, l1);
        split_h(v.z, h2, l2); split_h(v.w, h3, l3);
        reinterpret_cast<uint2*>(g_Wqh)[j] = make_uint2(packh2(h0, h1), packh2(h2, h3));
        reinterpret_cast<uint2*>(g_Wql)[j] = make_uint2(packh2(l0, l1), packh2(l2, l3));
    }
}

// transpose-split Wk: WkT[c][d] = Wk[d][c], hilo planes
__global__ void splitWkT(const float* __restrict__ Wk) {
    __shared__ float tile[32][33];
    const int d0 = blockIdx.x * 32, c0 = blockIdx.y * 32;
    const int tx = threadIdx.x, ty = threadIdx.y;
#pragma unroll
    for (int i = 0; i < 32; i += 8)
        tile[ty + i][tx] = Wk[(long)(d0 + ty + i) * CC + c0 + tx];
    __syncthreads();
    const int tid = ty * 32 + tx;
    const int cr = tid >> 3;           // 0..31 (c-local)
    const int q = tid & 7;             // 0..7  (d-quad)
    __half hh[4], ll[4];
#pragma unroll
    for (int j = 0; j < 4; j++)
        split_h(tile[4 * q + j][cr], hh[j], ll[j]);
    long ob = (long)(c0 + cr) * CC + d0 + 4 * q;
    *reinterpret_cast<uint2*>(&g_WkTh[ob]) = make_uint2(packh2(hh[0], hh[1]), packh2(hh[2], hh[3]));
    *reinterpret_cast<uint2*>(&g_WkTl[ob]) = make_uint2(packh2(ll[0], ll[1]), packh2(ll[2], ll[3]));
}

// MT[d'][c] = sum_c' Wout[d'][c'] * Wv[c'][c]   (fp32, then hilo split) — R13 version
__global__ void compute_MT(const float* __restrict__ Wv, const float* __restrict__ Wout) {
    __shared__ float As[32][33], Bs[32][33];
    const int bx = blockIdx.x, by = blockIdx.y;
    const int tx = threadIdx.x, ty = threadIdx.y;
    float acc[4] = {0.f, 0.f, 0.f, 0.f};
    for (int kt = 0; kt < CC / 32; kt++) {
#pragma unroll
        for (int i = 0; i < 32; i += 8) {
            As[ty + i][tx] = Wout[(long)(by * 32 + ty + i) * CC + kt * 32 + tx];
            Bs[ty + i][tx] = Wv[(long)(kt * 32 + ty + i) * CC + bx * 32 + tx];
        }
        __syncthreads();
#pragma unroll
        for (int k = 0; k < 32; k++) {
            float b = Bs[k][tx];
#pragma unroll
            for (int r = 0; r < 4; r++)
                acc[r] += As[ty * 4 + r][k] * b;
        }
        __syncthreads();
    }
#pragma unroll
    for (int r = 0; r < 4; r++) {
        long o = (long)(by * 32 + ty * 4 + r) * CC + bx * 32 + tx;
        __half h, l;
        split_h(acc[r], h, l);
        g_MTh[o] = h; g_MTl[o] = l;
    }
}

__global__ void node_max_kernel() {
    int i = blockIdx.x * blockDim.x + threadIdx.x;
    if (i >= BB * TT) return;
    int b = i / TT;
    unsigned long long p = g_colmax[i];
    unsigned int n = (unsigned int)(p & 0xffffffffu);
    atomicMax(&g_Mkey[b * NNODE + n], (unsigned int)(p >> 32));
}

__global__ void node_sum_kernel() {
    int i = blockIdx.x * blockDim.x + threadIdx.x;
    if (i >= BB * TT) return;
    int b = i / TT;
    unsigned long long p = g_colmax[i];
    unsigned int n = (unsigned int)(p & 0xffffffffu);
    int bn = b * NNODE + n;
    float m = funkey((unsigned int)(p >> 32));
    atomicAdd(&g_Z[bn], expf(m - funkey(g_Mkey[bn])));
}

// fused: att[bn][t] = w AND out[bn][:] += w * vw[b,t,:]  (out pre-initialized to bout)
__global__ void scatter_kernel(float* __restrict__ att, float* __restrict__ out) {
    int i = blockIdx.x;            // one block per (b, t)
    int b = i / TT;
    int t = i % TT;
    unsigned long long p = g_colmax[i];
    unsigned int n = (unsigned int)(p & 0xffffffffu);
    int bn = b * NNODE + n;
    float m = funkey((unsigned int)(p >> 32));
    float w = expf(m - funkey(g_Mkey[bn])) / g_Z[bn];
    if (threadIdx.x == 0) att[(long)bn * TT + t] = w;
    const float4* vrow = reinterpret_cast<const float4*>(g_vw + (long)i * CC);
    float* orow = out + (long)bn * CC;
    for (int c4 = threadIdx.x; c4 < CC / 4; c4 += blockDim.x) {
        float4 v4 = vrow[c4];
        atomicAdd(&orow[c4 * 4 + 0], w * v4.x);
        atomicAdd(&orow[c4 * 4 + 1], w * v4.y);
        atomicAdd(&orow[c4 * 4 + 2], w * v4.z);
        atomicAdd(&orow[c4 * 4 + 3], w * v4.w);
    }
}

// ============================ launch ============================
extern "C" void kernel_launch(void* const* d_in, const int* in_sizes, int n_in,
                              void* d_out, int out_size)
{
    const float* x    = (const float*)d_in[0];
    const float* Wq   = (const float*)d_in[1];
    const float* bq   = (const float*)d_in[2];
    const float* Wk   = (const float*)d_in[3];
    const float* Wv   = (const float*)d_in[4];
    const float* Wout = (const float*)d_in[5];
    const float* bout = (const float*)d_in[6];

    float* out = (float*)d_out;
    float* att = out + (long)BB * NNODE * CC;

    __half *xh, *xl, *xTh, *xTl, *Wqh, *Wql, *WkTh, *WkTl, *MTh, *MTl;
    __half *sh, *sl, *qh, *ql;
    float *vwp;
    unsigned long long* cm;
    cudaGetSymbolAddress((void**)&xh, g_xh);     cudaGetSymbolAddress((void**)&xl, g_xl);
    cudaGetSymbolAddress((void**)&xTh, g_xTh);   cudaGetSymbolAddress((void**)&xTl, g_xTl);
    cudaGetSymbolAddress((void**)&Wqh, g_Wqh);   cudaGetSymbolAddress((void**)&Wql, g_Wql);
    cudaGetSymbolAddress((void**)&WkTh, g_WkTh); cudaGetSymbolAddress((void**)&WkTl, g_WkTl);
    cudaGetSymbolAddress((void**)&MTh, g_MTh);   cudaGetSymbolAddress((void**)&MTl, g_MTl);
    cudaGetSymbolAddress((void**)&sh, g_sh);     cudaGetSymbolAddress((void**)&sl, g_sl);
    cudaGetSymbolAddress((void**)&qh, g_qh);     cudaGetSymbolAddress((void**)&ql, g_ql);
    cudaGetSymbolAddress((void**)&vwp, g_vw);
    cudaGetSymbolAddress((void**)&cm, g_colmax);

    cudaFuncSetAttribute(gemm_mma<2,3>, cudaFuncAttributeMaxDynamicSharedMemorySize, SMEM_SZ);
    cudaFuncSetAttribute(gemm_mma<0,1>, cudaFuncAttributeMaxDynamicSharedMemorySize, SMEM_SZ);
    cudaFuncSetAttribute(gemm_mma<3,3>, cudaFuncAttributeMaxDynamicSharedMemorySize, SMEM_SZ);
    cudaFuncSetAttribute(gemm_mma<4,3>, cudaFuncAttributeMaxDynamicSharedMemorySize, SMEM_SZ);

    const float scale = 1.0f / sqrtf((float)CC);

    init_kernel<<<2048, 256>>>(out, bout);
    split_x<<<dim3(TT / 32, CC / 32, BB), dim3(32, 8)>>>(x);
    splitWq<<<2048, 256>>>(Wq);
    splitWkT<<<dim3(CC / 32, CC / 32), dim3(32, 8)>>>(Wk);
    compute_MT<<<dim3(CC / 32, CC / 32), dim3(32, 8)>>>(Wv, Wout);

    // q[b] = Wq @ xT[b]^T + bq -> hilo (3-term)
    gemm_mma<3,3><<<dim3(4, 8, BB), 256, SMEM_SZ>>>(
        Wqh, Wql, xTh, xTl, bq, nullptr, qh, ql, CC, TT,
        0, (long)CC * TT, (long)NNODE * CC, 0.f, nullptr, 0);
    // qWk[b][n,c] = q[b] @ WkT^T -> hilo (3-term)   (M=1024, N=512, K=512)
    gemm_mma<2,3><<<dim3(4, 8, BB), 256, SMEM_SZ>>>(
        qh, ql, WkTh, WkTl, nullptr, nullptr, sh, sl, CC, CC,
        (long)NNODE * CC, 0, (long)NNODE * CC, 0.f, nullptr, 0);
    // vw = x @ MT^T -> plain fp32 (1-term: hh only)
    gemm_mma<0,1><<<dim3(4, 128, 1), 256, SMEM_SZ>>>(
        xh, xl, MTh, MTl, nullptr, vwp, nullptr, nullptr, CC, CC, 0, 0, 0, 0.f, nullptr, 0);
    // sim[b] = scale * x[b] @ qWk[b]^T, token-major, fused argmax (3-term)
    gemm_mma<4,3><<<dim3(NNODE / 128, TT / 128, BB), 256, SMEM_SZ>>>(
        xh, xl, sh, sl, nullptr, nullptr, nullptr, nullptr, NNODE, CC,
        (long)TT * CC, (long)NNODE * CC, 0, scale, cm, (long)TT);

    cudaMemsetAsync(att, 0, (size_t)BB * NNODE * TT * sizeof(float), 0);
    node_max_kernel<<<(BB * TT) / 256, 256>>>();
    node_sum_kernel<<<(BB * TT) / 256, 256>>>();
    scatter_kernel<<<BB * TT, 128>>>(att, out);
}